// round 8
// baseline (speedup 1.0000x reference)
#include <cuda_runtime.h>
#include <cuda_fp16.h>
#include <mma.h>
#include <cstdint>

using namespace nvcuda;

#define N_NODES_C 50000
#define N_PAIRS_C 800000
#define NHEADS_C 4
#define HEAD_DIM_C 64
#define NF_C 256   // NHEADS*HEAD_DIM
#define CAP 96
#define OVF_CAP 4096

// scratch (allocation-free rule: __device__ globals)
__device__ __half g_q[N_NODES_C * NF_C];
__device__ __half g_k[N_NODES_C * NF_C];
__device__ __half g_v[N_NODES_C * NF_C];
__device__ __half g_wh[3 * NHEADS_C * HEAD_DIM_C * HEAD_DIM_C]; // fp16 W (q,k,v)
__device__ float  g_alpha[(size_t)N_PAIRS_C * NHEADS_C];

__device__ int   g_cnt[N_NODES_C];
__device__ int2  g_bkt[(size_t)N_NODES_C * CAP];
__device__ int   g_ovf_cnt;
__device__ int   g_ovf[OVF_CAP];

// ---------------------------------------------------------------------------
// Convert weights to fp16: g_wh[mat*16384 + h*4096 + e*64 + d]
// ---------------------------------------------------------------------------
__global__ void conv_w_kernel(const float* __restrict__ Wq,
                              const float* __restrict__ Wk,
                              const float* __restrict__ Wv) {
    int t = blockIdx.x * blockDim.x + threadIdx.x;
    int base = t * 4;
    if (base >= 3 * 16384) return;
    int mat = base >> 14;
    int r   = base & 16383;
    const float* src = (mat == 0) ? Wq : ((mat == 1) ? Wk : Wv);
    float4 f = *(const float4*)(src + r);
    __half2 h0 = __floats2half2_rn(f.x, f.y);
    __half2 h1 = __floats2half2_rn(f.z, f.w);
    uint2 out;
    out.x = *(const unsigned*)&h0;
    out.y = *(const unsigned*)&h1;
    *(uint2*)(g_wh + mat * 16384 + r) = out;
}

// ---------------------------------------------------------------------------
// Block-tiled tensor-core projection.
// Block = 128 nodes, 8 warps (warp w owns rows w*16..w*16+15).
// smem: stage[8][256] f32 | sW (all 3x4 64x64 fp16 mats) | sX[128][264] fp16
// X converted fp32->fp16 in-kernel (no conv_x round trip).
// ---------------------------------------------------------------------------
#define PM_TILE 128
#define PROJ_THREADS 256
#define SX_LD 264                     // 256 + 8 pad (keeps 16B-aligned rows)
#define SMEM_STAGE_F (8 * 256)
#define SMEM_W_H (3 * NHEADS_C * 64 * 64)          // 49152 halfs
#define SMEM_X_H (PM_TILE * SX_LD)                 // 33792 halfs
#define PROJ_SMEM_BYTES (SMEM_STAGE_F * 4 + (SMEM_W_H + SMEM_X_H) * 2)

__global__ void __launch_bounds__(PROJ_THREADS)
proj_wmma_kernel(const float* __restrict__ x) {
    extern __shared__ float smraw[];
    float*  stage = smraw;                                   // 8*256 f32
    __half* sW = (__half*)(smraw + SMEM_STAGE_F);            // 49152 halfs
    __half* sX = sW + SMEM_W_H;                              // 128*264 halfs

    const int tid  = threadIdx.x;
    const int warp = tid >> 5;
    const int lane = tid & 31;
    const int n0   = blockIdx.x * PM_TILE;

    // load all weights into smem (flat copy, 6144 uint4)
    for (int i = tid; i < SMEM_W_H / 8; i += PROJ_THREADS)
        ((uint4*)sW)[i] = ((const uint4*)g_wh)[i];

    // load x tile, convert fp32 -> fp16 into padded smem
    for (int i = tid; i < PM_TILE * 64; i += PROJ_THREADS) {
        int row = i >> 6, c4 = i & 63;
        int n = n0 + row;
        uint2 pack;
        if (n < N_NODES_C) {
            float4 f = __ldg((const float4*)(x + (size_t)n * NF_C + c4 * 4));
            __half2 h0 = __floats2half2_rn(f.x, f.y);
            __half2 h1 = __floats2half2_rn(f.z, f.w);
            pack.x = *(const unsigned*)&h0;
            pack.y = *(const unsigned*)&h1;
        } else {
            pack.x = 0u; pack.y = 0u;
        }
        *(uint2*)(sX + row * SX_LD + c4 * 4) = pack;
    }
    __syncthreads();

    const __half* Arow = sX + warp * 16 * SX_LD;
    float* st = stage + warp * 256;
    const int srow = lane >> 1;          // 0..15
    const int sseg = lane & 1;           // 0..1
    const int nrow = n0 + warp * 16 + srow;
    const bool rok = (nrow < N_NODES_C);

    for (int h = 0; h < NHEADS_C; h++) {
        wmma::fragment<wmma::matrix_a, 16, 16, 16, __half, wmma::row_major> a[4];
#pragma unroll
        for (int kt = 0; kt < 4; kt++)
            wmma::load_matrix_sync(a[kt], Arow + h * HEAD_DIM_C + kt * 16, SX_LD);

        for (int mat = 0; mat < 3; mat++) {
            const __half* Wb = sW + (mat * NHEADS_C + h) * 4096;
            __half* out = (mat == 0) ? g_q : ((mat == 1) ? g_k : g_v);
#pragma unroll
            for (int et = 0; et < 4; et++) {
                wmma::fragment<wmma::accumulator, 16, 16, 16, float> c;
                wmma::fill_fragment(c, 0.0f);
#pragma unroll
                for (int kt = 0; kt < 4; kt++) {
                    wmma::fragment<wmma::matrix_b, 16, 16, 16, __half, wmma::col_major> b;
                    wmma::load_matrix_sync(b, Wb + et * 16 * 64 + kt * 16, 64);
                    wmma::mma_sync(c, a[kt], b, c);
                }
                wmma::store_matrix_sync(st, c, 16, wmma::mem_row_major);
                __syncwarp();
                if (rok) {
                    const float* src = st + srow * 16 + sseg * 8;
                    __half2 o0 = __floats2half2_rn(src[0], src[1]);
                    __half2 o1 = __floats2half2_rn(src[2], src[3]);
                    __half2 o2 = __floats2half2_rn(src[4], src[5]);
                    __half2 o3 = __floats2half2_rn(src[6], src[7]);
                    uint4 pack;
                    pack.x = *(const unsigned*)&o0;
                    pack.y = *(const unsigned*)&o1;
                    pack.z = *(const unsigned*)&o2;
                    pack.w = *(const unsigned*)&o3;
                    *(uint4*)(out + (size_t)nrow * NF_C + h * HEAD_DIM_C
                              + et * 16 + sseg * 8) = pack;
                }
                __syncwarp();
            }
        }
    }
}

// ---------------------------------------------------------------------------
// Bucket build
// ---------------------------------------------------------------------------
__global__ void zero_cnt_kernel() {
    int t = blockIdx.x * blockDim.x + threadIdx.x;
    if (t < N_NODES_C) g_cnt[t] = 0;
    if (t == 0) g_ovf_cnt = 0;
}

__global__ void bucket_kernel(const int* __restrict__ idx_i,
                              const int* __restrict__ idx_j) {
    int e = blockIdx.x * blockDim.x + threadIdx.x;
    if (e >= N_PAIRS_C) return;
    int i = idx_i[e];
    int pos = atomicAdd(&g_cnt[i], 1);
    if (pos < CAP) {
        g_bkt[(size_t)i * CAP + pos] = make_int2(e, idx_j[e]);
    } else {
        int p = atomicAdd(&g_ovf_cnt, 1);
        if (p < OVF_CAP) g_ovf[p] = e;
    }
}

// ---------------------------------------------------------------------------
// dot helper
// ---------------------------------------------------------------------------
__device__ __forceinline__ float dot8_h(uint4 qu, uint4 ku, float4 w0, float4 w1) {
    const __half2* q2 = (const __half2*)&qu;
    const __half2* k2 = (const __half2*)&ku;
    float2 qf0 = __half22float2(q2[0]);
    float2 qf1 = __half22float2(q2[1]);
    float2 qf2 = __half22float2(q2[2]);
    float2 qf3 = __half22float2(q2[3]);
    float2 kf0 = __half22float2(k2[0]);
    float2 kf1 = __half22float2(k2[1]);
    float2 kf2 = __half22float2(k2[2]);
    float2 kf3 = __half22float2(k2[3]);
    float s;
    s  = qf0.x * w0.x * kf0.x;
    s += qf0.y * w0.y * kf0.y;
    s += qf1.x * w0.z * kf1.x;
    s += qf1.y * w0.w * kf1.y;
    s += qf2.x * w1.x * kf2.x;
    s += qf2.y * w1.y * kf2.y;
    s += qf3.x * w1.z * kf3.x;
    s += qf3.y * w1.w * kf3.y;
    return s;
}

// ---------------------------------------------------------------------------
// Kernel A: alpha stream.  One warp per 4 edges, front-batched loads.
// ---------------------------------------------------------------------------
__global__ void __launch_bounds__(256)
alpha_kernel(const float* __restrict__ w_ij,
             const int* __restrict__ idx_i,
             const int* __restrict__ idx_j,
             const float* __restrict__ phi) {
    int warp = (blockIdx.x * blockDim.x + threadIdx.x) >> 5;
    int lane = threadIdx.x & 31;
    int e0 = warp * 4;
    if (e0 >= N_PAIRS_C) return;     // N_PAIRS % 4 == 0
    int off = lane * 8;

    int ii[4], jj[4];
    float pp[4];
#pragma unroll
    for (int r = 0; r < 4; r++) {
        ii[r] = __ldg(&idx_i[e0 + r]);
        jj[r] = __ldg(&idx_j[e0 + r]);
        pp[r] = __ldg(&phi[e0 + r]);
    }

    float4 wa[4], wb[4];
#pragma unroll
    for (int r = 0; r < 4; r++) {
        const float4* wp = (const float4*)(w_ij + (size_t)(e0 + r) * NF_C + off);
        wa[r] = __ldcs(wp);
        wb[r] = __ldcs(wp + 1);
    }
    uint4 qu[4], ku[4];
#pragma unroll
    for (int r = 0; r < 4; r++) {
        qu[r] = __ldg((const uint4*)(g_q + (size_t)ii[r] * NF_C + off));
        ku[r] = __ldg((const uint4*)(g_k + (size_t)jj[r] * NF_C + off));
    }

    float s[4];
#pragma unroll
    for (int r = 0; r < 4; r++)
        s[r] = dot8_h(qu[r], ku[r], wa[r], wb[r]);

#pragma unroll
    for (int r = 0; r < 4; r++) {
        s[r] += __shfl_xor_sync(0xffffffffu, s[r], 1);
        s[r] += __shfl_xor_sync(0xffffffffu, s[r], 2);
        s[r] += __shfl_xor_sync(0xffffffffu, s[r], 4);
    }

    if ((lane & 7) == 0) {
        int h = lane >> 3;
#pragma unroll
        for (int r = 0; r < 4; r++)
            g_alpha[(size_t)(e0 + r) * NHEADS_C + h] = s[r] * 0.125f * pp[r];
    }
}

// ---------------------------------------------------------------------------
// Kernel B: gather-accumulate.  One warp per node, 4-edge unroll.
// ---------------------------------------------------------------------------
__device__ __forceinline__ void acc_v(float al, uint4 vu, float* a) {
    const __half2* v2 = (const __half2*)&vu;
    float2 f;
    f = __half22float2(v2[0]); a[0] = fmaf(al, f.x, a[0]); a[1] = fmaf(al, f.y, a[1]);
    f = __half22float2(v2[1]); a[2] = fmaf(al, f.x, a[2]); a[3] = fmaf(al, f.y, a[3]);
    f = __half22float2(v2[2]); a[4] = fmaf(al, f.x, a[4]); a[5] = fmaf(al, f.y, a[5]);
    f = __half22float2(v2[3]); a[6] = fmaf(al, f.x, a[6]); a[7] = fmaf(al, f.y, a[7]);
}

__global__ void __launch_bounds__(256)
accum_kernel(float* __restrict__ y) {
    int node = (blockIdx.x * blockDim.x + threadIdx.x) >> 5;
    int lane = threadIdx.x & 31;
    if (node >= N_NODES_C) return;

    int deg = g_cnt[node];
    if (deg > CAP) deg = CAP;
    const size_t base = (size_t)node * CAP;
    const int off  = lane * 8;
    const int head = lane >> 3;

    float a[8] = {0.f, 0.f, 0.f, 0.f, 0.f, 0.f, 0.f, 0.f};

    int t = 0;
    for (; t + 4 <= deg; t += 4) {
        int2 m[4];
        float al[4];
        uint4 vu[4];
#pragma unroll
        for (int r = 0; r < 4; r++) m[r] = g_bkt[base + t + r];
#pragma unroll
        for (int r = 0; r < 4; r++) {
            al[r] = __ldg(&g_alpha[(size_t)m[r].x * NHEADS_C + head]);
            vu[r] = __ldg((const uint4*)(g_v + (size_t)m[r].y * NF_C + off));
        }
#pragma unroll
        for (int r = 0; r < 4; r++) acc_v(al[r], vu[r], a);
    }
    for (; t < deg; t++) {
        int2 m0 = g_bkt[base + t];
        float al0 = __ldg(&g_alpha[(size_t)m0.x * NHEADS_C + head]);
        uint4 vu0 = __ldg((const uint4*)(g_v + (size_t)m0.y * NF_C + off));
        acc_v(al0, vu0, a);
    }

    float4* yp = (float4*)(y + (size_t)node * NF_C + off);
    yp[0] = make_float4(a[0], a[1], a[2], a[3]);
    yp[1] = make_float4(a[4], a[5], a[6], a[7]);
}

// ---------------------------------------------------------------------------
// Overflow fallback
// ---------------------------------------------------------------------------
__global__ void overflow_kernel(const int* __restrict__ idx_i,
                                const int* __restrict__ idx_j,
                                float* __restrict__ y) {
    int n = g_ovf_cnt;
    if (n > OVF_CAP) n = OVF_CAP;
    int lane = threadIdx.x & 31;
    for (int t = (int)(threadIdx.x >> 5); t < n; t += (int)(blockDim.x >> 5)) {
        int e = g_ovf[t];
        int i = idx_i[e];
        int j = idx_j[e];
        int off = lane * 8;
        int head = lane >> 3;

        float alpha = g_alpha[(size_t)e * NHEADS_C + head];
        uint4 vu = *(const uint4*)(g_v + (size_t)j * NF_C + off);
        const __half2* v2 = (const __half2*)&vu;
        float2 f0 = __half22float2(v2[0]);
        float2 f1 = __half22float2(v2[1]);
        float2 f2 = __half22float2(v2[2]);
        float2 f3 = __half22float2(v2[3]);
        float* yp = y + (size_t)i * NF_C + off;
        atomicAdd(yp + 0, alpha * f0.x);
        atomicAdd(yp + 1, alpha * f0.y);
        atomicAdd(yp + 2, alpha * f1.x);
        atomicAdd(yp + 3, alpha * f1.y);
        atomicAdd(yp + 4, alpha * f2.x);
        atomicAdd(yp + 5, alpha * f2.y);
        atomicAdd(yp + 6, alpha * f3.x);
        atomicAdd(yp + 7, alpha * f3.y);
    }
}

// ---------------------------------------------------------------------------
// launch
// ---------------------------------------------------------------------------
extern "C" void kernel_launch(void* const* d_in, const int* in_sizes, int n_in,
                              void* d_out, int out_size) {
    const float* x     = (const float*)d_in[0];
    const float* w_ij  = (const float*)d_in[1];
    const int*   idx_i = (const int*)d_in[2];
    const int*   idx_j = (const int*)d_in[3];
    const float* phi   = (const float*)d_in[4];
    const float* Wq    = (const float*)d_in[5];
    const float* Wk    = (const float*)d_in[6];
    const float* Wv    = (const float*)d_in[7];
    float* y = (float*)d_out;

    // fp16 weight conversion
    conv_w_kernel<<<48, 256>>>(Wq, Wk, Wv);

    // bucket build
    zero_cnt_kernel<<<(N_NODES_C + 255) / 256, 256>>>();
    bucket_kernel<<<(N_PAIRS_C + 255) / 256, 256>>>(idx_i, idx_j);

    // block-tiled tensor-core projection
    cudaFuncSetAttribute(proj_wmma_kernel,
                         cudaFuncAttributeMaxDynamicSharedMemorySize,
                         PROJ_SMEM_BYTES);
    int pblocks = (N_NODES_C + PM_TILE - 1) / PM_TILE;   // 391
    proj_wmma_kernel<<<pblocks, PROJ_THREADS, PROJ_SMEM_BYTES>>>(x);

    // A: alpha stream (4 edges per warp)
    int ablocks = (N_PAIRS_C / 4 + 7) / 8;
    alpha_kernel<<<ablocks, 256>>>(w_ij, idx_i, idx_j, phi);

    // B: gather-accumulate
    int nblocks = (N_NODES_C + 7) / 8;
    accum_kernel<<<nblocks, 256>>>(y);

    // overflow (usually empty)
    overflow_kernel<<<1, 256>>>(idx_i, idx_j, y);
}

// round 9
// speedup vs baseline: 1.2736x; 1.2736x over previous
#include <cuda_runtime.h>
#include <cuda_fp16.h>
#include <mma.h>
#include <cstdint>

using namespace nvcuda;

#define N_NODES_C 50000
#define N_PAIRS_C 800000
#define NHEADS_C 4
#define HEAD_DIM_C 64
#define NF_C 256   // NHEADS*HEAD_DIM
#define CAP 96
#define OVF_CAP 4096

// scratch (allocation-free rule: __device__ globals)
__device__ __half g_q[N_NODES_C * NF_C];
__device__ __half g_k[N_NODES_C * NF_C];
__device__ __half g_v[N_NODES_C * NF_C];
__device__ __half g_xh[(size_t)N_NODES_C * NF_C];               // fp16 x
__device__ __half g_wh[3 * NHEADS_C * HEAD_DIM_C * HEAD_DIM_C]; // fp16 W
__device__ float  g_alpha[(size_t)N_PAIRS_C * NHEADS_C];

__device__ int   g_cnt[N_NODES_C];
__device__ int2  g_bkt[(size_t)N_NODES_C * CAP];
__device__ int   g_ovf_cnt;
__device__ int   g_ovf[OVF_CAP];

// ---------------------------------------------------------------------------
// Convert weights to fp16: g_wh[mat*16384 + h*4096 + e*64 + d]
// ---------------------------------------------------------------------------
__global__ void conv_w_kernel(const float* __restrict__ Wq,
                              const float* __restrict__ Wk,
                              const float* __restrict__ Wv) {
    int t = blockIdx.x * blockDim.x + threadIdx.x;
    int base = t * 4;
    if (base >= 3 * 16384) return;
    int mat = base >> 14;
    int r   = base & 16383;
    const float* src = (mat == 0) ? Wq : ((mat == 1) ? Wk : Wv);
    float4 f = *(const float4*)(src + r);
    __half2 h0 = __floats2half2_rn(f.x, f.y);
    __half2 h1 = __floats2half2_rn(f.z, f.w);
    uint2 out;
    out.x = *(const unsigned*)&h0;
    out.y = *(const unsigned*)&h1;
    *(uint2*)(g_wh + mat * 16384 + r) = out;
}

// ---------------------------------------------------------------------------
// Convert x to fp16
// ---------------------------------------------------------------------------
__global__ void conv_x_kernel(const float* __restrict__ x) {
    size_t t = (size_t)blockIdx.x * blockDim.x + threadIdx.x;
    size_t base = t * 8;
    if (base >= (size_t)N_NODES_C * NF_C) return;
    float4 f0 = *(const float4*)(x + base);
    float4 f1 = *(const float4*)(x + base + 4);
    __half2 h0 = __floats2half2_rn(f0.x, f0.y);
    __half2 h1 = __floats2half2_rn(f0.z, f0.w);
    __half2 h2 = __floats2half2_rn(f1.x, f1.y);
    __half2 h3 = __floats2half2_rn(f1.z, f1.w);
    uint4 out;
    out.x = *(const unsigned*)&h0;
    out.y = *(const unsigned*)&h1;
    out.z = *(const unsigned*)&h2;
    out.w = *(const unsigned*)&h3;
    *(uint4*)(g_xh + base) = out;
}

// ---------------------------------------------------------------------------
// Tensor-core projection: warp per 16-node m-tile (Round-7 structure),
// but W staged in smem (96KB -> 2 blocks/SM, B frags via LDSM).
// dynamic smem: float stage[8][256] | __half sW[49152]
// ---------------------------------------------------------------------------
#define PROJ_WARPS 8
#define SMEM_STAGE_F (PROJ_WARPS * 256)
#define SMEM_W_H (3 * NHEADS_C * 64 * 64)      // 49152 halfs
#define PROJ_SMEM_BYTES (SMEM_STAGE_F * 4 + SMEM_W_H * 2)   // 106496 B

__global__ void __launch_bounds__(PROJ_WARPS * 32)
proj_wmma_kernel() {
    extern __shared__ float smraw[];
    float*  stage = smraw;
    __half* sW = (__half*)(smraw + SMEM_STAGE_F);

    int tid  = threadIdx.x;
    int warp = tid >> 5;
    int lane = tid & 31;

    // stage all weights (6144 uint4)
    for (int i = tid; i < SMEM_W_H / 8; i += PROJ_WARPS * 32)
        ((uint4*)sW)[i] = ((const uint4*)g_wh)[i];
    __syncthreads();

    int tile = blockIdx.x * PROJ_WARPS + warp;
    if (tile >= N_NODES_C / 16) return;   // 50000 % 16 == 0
    int n0 = tile * 16;

    const __half* A0 = g_xh + (size_t)n0 * NF_C;
    float* st = stage + warp * 256;
    const int srow = lane >> 1;
    const int sseg = lane & 1;

    for (int h = 0; h < NHEADS_C; h++) {
        wmma::fragment<wmma::matrix_a, 16, 16, 16, __half, wmma::row_major> a[4];
#pragma unroll
        for (int kt = 0; kt < 4; kt++)
            wmma::load_matrix_sync(a[kt], A0 + h * HEAD_DIM_C + kt * 16, NF_C);

        for (int mat = 0; mat < 3; mat++) {
            const __half* Wb = sW + (mat * NHEADS_C + h) * 4096;
            __half* out = (mat == 0) ? g_q : ((mat == 1) ? g_k : g_v);
#pragma unroll
            for (int et = 0; et < 4; et++) {
                wmma::fragment<wmma::accumulator, 16, 16, 16, float> c;
                wmma::fill_fragment(c, 0.0f);
#pragma unroll
                for (int kt = 0; kt < 4; kt++) {
                    wmma::fragment<wmma::matrix_b, 16, 16, 16, __half, wmma::col_major> b;
                    wmma::load_matrix_sync(b, Wb + et * 16 * 64 + kt * 16, 64);
                    wmma::mma_sync(c, a[kt], b, c);
                }
                wmma::store_matrix_sync(st, c, 16, wmma::mem_row_major);
                __syncwarp();
                const float* src = st + srow * 16 + sseg * 8;
                __half2 o0 = __floats2half2_rn(src[0], src[1]);
                __half2 o1 = __floats2half2_rn(src[2], src[3]);
                __half2 o2 = __floats2half2_rn(src[4], src[5]);
                __half2 o3 = __floats2half2_rn(src[6], src[7]);
                uint4 pack;
                pack.x = *(const unsigned*)&o0;
                pack.y = *(const unsigned*)&o1;
                pack.z = *(const unsigned*)&o2;
                pack.w = *(const unsigned*)&o3;
                *(uint4*)(out + (size_t)(n0 + srow) * NF_C + h * HEAD_DIM_C
                          + et * 16 + sseg * 8) = pack;
                __syncwarp();
            }
        }
    }
}

// ---------------------------------------------------------------------------
// Bucket build
// ---------------------------------------------------------------------------
__global__ void zero_cnt_kernel() {
    int t = blockIdx.x * blockDim.x + threadIdx.x;
    if (t < N_NODES_C) g_cnt[t] = 0;
    if (t == 0) g_ovf_cnt = 0;
}

__global__ void bucket_kernel(const int* __restrict__ idx_i,
                              const int* __restrict__ idx_j) {
    int e = blockIdx.x * blockDim.x + threadIdx.x;
    if (e >= N_PAIRS_C) return;
    int i = idx_i[e];
    int pos = atomicAdd(&g_cnt[i], 1);
    if (pos < CAP) {
        g_bkt[(size_t)i * CAP + pos] = make_int2(e, idx_j[e]);
    } else {
        int p = atomicAdd(&g_ovf_cnt, 1);
        if (p < OVF_CAP) g_ovf[p] = e;
    }
}

// ---------------------------------------------------------------------------
// dot helper
// ---------------------------------------------------------------------------
__device__ __forceinline__ float dot8_h(uint4 qu, uint4 ku, float4 w0, float4 w1) {
    const __half2* q2 = (const __half2*)&qu;
    const __half2* k2 = (const __half2*)&ku;
    float2 qf0 = __half22float2(q2[0]);
    float2 qf1 = __half22float2(q2[1]);
    float2 qf2 = __half22float2(q2[2]);
    float2 qf3 = __half22float2(q2[3]);
    float2 kf0 = __half22float2(k2[0]);
    float2 kf1 = __half22float2(k2[1]);
    float2 kf2 = __half22float2(k2[2]);
    float2 kf3 = __half22float2(k2[3]);
    float s;
    s  = qf0.x * w0.x * kf0.x;
    s += qf0.y * w0.y * kf0.y;
    s += qf1.x * w0.z * kf1.x;
    s += qf1.y * w0.w * kf1.y;
    s += qf2.x * w1.x * kf2.x;
    s += qf2.y * w1.y * kf2.y;
    s += qf3.x * w1.z * kf3.x;
    s += qf3.y * w1.w * kf3.y;
    return s;
}

// ---------------------------------------------------------------------------
// Kernel A: alpha stream (2-edge unroll, measured-good version)
// ---------------------------------------------------------------------------
__global__ void __launch_bounds__(256)
alpha_kernel(const float* __restrict__ w_ij,
             const int* __restrict__ idx_i,
             const int* __restrict__ idx_j,
             const float* __restrict__ phi) {
    int warp = (blockIdx.x * blockDim.x + threadIdx.x) >> 5;
    int lane = threadIdx.x & 31;
    int e0 = warp * 2;
    if (e0 >= N_PAIRS_C) return;
    int e1 = e0 + 1;
    int off = lane * 8;

    int   i0 = __ldg(&idx_i[e0]), i1 = __ldg(&idx_i[e1]);
    int   j0 = __ldg(&idx_j[e0]), j1 = __ldg(&idx_j[e1]);
    float p0 = __ldg(&phi[e0]),   p1 = __ldg(&phi[e1]);

    const float4* wp0 = (const float4*)(w_ij + (size_t)e0 * NF_C + off);
    const float4* wp1 = (const float4*)(w_ij + (size_t)e1 * NF_C + off);
    float4 w00 = __ldcs(wp0);
    float4 w01 = __ldcs(wp0 + 1);
    float4 w10 = __ldcs(wp1);
    float4 w11 = __ldcs(wp1 + 1);

    uint4 qu0 = __ldg((const uint4*)(g_q + (size_t)i0 * NF_C + off));
    uint4 ku0 = __ldg((const uint4*)(g_k + (size_t)j0 * NF_C + off));
    uint4 qu1 = __ldg((const uint4*)(g_q + (size_t)i1 * NF_C + off));
    uint4 ku1 = __ldg((const uint4*)(g_k + (size_t)j1 * NF_C + off));

    float s0 = dot8_h(qu0, ku0, w00, w01);
    float s1 = dot8_h(qu1, ku1, w10, w11);

    s0 += __shfl_xor_sync(0xffffffffu, s0, 1);
    s1 += __shfl_xor_sync(0xffffffffu, s1, 1);
    s0 += __shfl_xor_sync(0xffffffffu, s0, 2);
    s1 += __shfl_xor_sync(0xffffffffu, s1, 2);
    s0 += __shfl_xor_sync(0xffffffffu, s0, 4);
    s1 += __shfl_xor_sync(0xffffffffu, s1, 4);

    if ((lane & 7) == 0) {
        int h = lane >> 3;
        g_alpha[(size_t)e0 * NHEADS_C + h] = s0 * 0.125f * p0;
        g_alpha[(size_t)e1 * NHEADS_C + h] = s1 * 0.125f * p1;
    }
}

// ---------------------------------------------------------------------------
// Kernel B: gather-accumulate (2-edge unroll, measured-good version)
// ---------------------------------------------------------------------------
__global__ void __launch_bounds__(256)
accum_kernel(float* __restrict__ y) {
    int node = (blockIdx.x * blockDim.x + threadIdx.x) >> 5;
    int lane = threadIdx.x & 31;
    if (node >= N_NODES_C) return;

    int deg = g_cnt[node];
    if (deg > CAP) deg = CAP;
    const size_t base = (size_t)node * CAP;
    const int off  = lane * 8;
    const int head = lane >> 3;

    float a0 = 0.f, a1 = 0.f, a2 = 0.f, a3 = 0.f;
    float a4 = 0.f, a5 = 0.f, a6 = 0.f, a7 = 0.f;

    int t = 0;
    for (; t + 2 <= deg; t += 2) {
        int2 m0 = g_bkt[base + t];
        int2 m1 = g_bkt[base + t + 1];
        float al0 = __ldg(&g_alpha[(size_t)m0.x * NHEADS_C + head]);
        float al1 = __ldg(&g_alpha[(size_t)m1.x * NHEADS_C + head]);
        uint4 vu0 = __ldg((const uint4*)(g_v + (size_t)m0.y * NF_C + off));
        uint4 vu1 = __ldg((const uint4*)(g_v + (size_t)m1.y * NF_C + off));

        const __half2* v20 = (const __half2*)&vu0;
        const __half2* v21 = (const __half2*)&vu1;
        float2 f;
        f = __half22float2(v20[0]); a0 = fmaf(al0, f.x, a0); a1 = fmaf(al0, f.y, a1);
        f = __half22float2(v20[1]); a2 = fmaf(al0, f.x, a2); a3 = fmaf(al0, f.y, a3);
        f = __half22float2(v20[2]); a4 = fmaf(al0, f.x, a4); a5 = fmaf(al0, f.y, a5);
        f = __half22float2(v20[3]); a6 = fmaf(al0, f.x, a6); a7 = fmaf(al0, f.y, a7);
        f = __half22float2(v21[0]); a0 = fmaf(al1, f.x, a0); a1 = fmaf(al1, f.y, a1);
        f = __half22float2(v21[1]); a2 = fmaf(al1, f.x, a2); a3 = fmaf(al1, f.y, a3);
        f = __half22float2(v21[2]); a4 = fmaf(al1, f.x, a4); a5 = fmaf(al1, f.y, a5);
        f = __half22float2(v21[3]); a6 = fmaf(al1, f.x, a6); a7 = fmaf(al1, f.y, a7);
    }
    if (t < deg) {
        int2 m0 = g_bkt[base + t];
        float al0 = __ldg(&g_alpha[(size_t)m0.x * NHEADS_C + head]);
        uint4 vu0 = __ldg((const uint4*)(g_v + (size_t)m0.y * NF_C + off));
        const __half2* v20 = (const __half2*)&vu0;
        float2 f;
        f = __half22float2(v20[0]); a0 = fmaf(al0, f.x, a0); a1 = fmaf(al0, f.y, a1);
        f = __half22float2(v20[1]); a2 = fmaf(al0, f.x, a2); a3 = fmaf(al0, f.y, a3);
        f = __half22float2(v20[2]); a4 = fmaf(al0, f.x, a4); a5 = fmaf(al0, f.y, a5);
        f = __half22float2(v20[3]); a6 = fmaf(al0, f.x, a6); a7 = fmaf(al0, f.y, a7);
    }

    float4* yp = (float4*)(y + (size_t)node * NF_C + off);
    yp[0] = make_float4(a0, a1, a2, a3);
    yp[1] = make_float4(a4, a5, a6, a7);
}

// ---------------------------------------------------------------------------
// Overflow fallback
// ---------------------------------------------------------------------------
__global__ void overflow_kernel(const int* __restrict__ idx_i,
                                const int* __restrict__ idx_j,
                                float* __restrict__ y) {
    int n = g_ovf_cnt;
    if (n > OVF_CAP) n = OVF_CAP;
    int lane = threadIdx.x & 31;
    for (int t = (int)(threadIdx.x >> 5); t < n; t += (int)(blockDim.x >> 5)) {
        int e = g_ovf[t];
        int i = idx_i[e];
        int j = idx_j[e];
        int off = lane * 8;
        int head = lane >> 3;

        float alpha = g_alpha[(size_t)e * NHEADS_C + head];
        uint4 vu = *(const uint4*)(g_v + (size_t)j * NF_C + off);
        const __half2* v2 = (const __half2*)&vu;
        float2 f0 = __half22float2(v2[0]);
        float2 f1 = __half22float2(v2[1]);
        float2 f2 = __half22float2(v2[2]);
        float2 f3 = __half22float2(v2[3]);
        float* yp = y + (size_t)i * NF_C + off;
        atomicAdd(yp + 0, alpha * f0.x);
        atomicAdd(yp + 1, alpha * f0.y);
        atomicAdd(yp + 2, alpha * f1.x);
        atomicAdd(yp + 3, alpha * f1.y);
        atomicAdd(yp + 4, alpha * f2.x);
        atomicAdd(yp + 5, alpha * f2.y);
        atomicAdd(yp + 6, alpha * f3.x);
        atomicAdd(yp + 7, alpha * f3.y);
    }
}

// ---------------------------------------------------------------------------
// launch
// ---------------------------------------------------------------------------
extern "C" void kernel_launch(void* const* d_in, const int* in_sizes, int n_in,
                              void* d_out, int out_size) {
    const float* x     = (const float*)d_in[0];
    const float* w_ij  = (const float*)d_in[1];
    const int*   idx_i = (const int*)d_in[2];
    const int*   idx_j = (const int*)d_in[3];
    const float* phi   = (const float*)d_in[4];
    const float* Wq    = (const float*)d_in[5];
    const float* Wk    = (const float*)d_in[6];
    const float* Wv    = (const float*)d_in[7];
    float* y = (float*)d_out;

    // fp16 conversions
    conv_w_kernel<<<48, 256>>>(Wq, Wk, Wv);
    conv_x_kernel<<<6250, 256>>>(x);

    // bucket build
    zero_cnt_kernel<<<(N_NODES_C + 255) / 256, 256>>>();
    bucket_kernel<<<(N_PAIRS_C + 255) / 256, 256>>>(idx_i, idx_j);

    // tensor-core projection (W in smem, 2 blocks/SM)
    cudaFuncSetAttribute(proj_wmma_kernel,
                         cudaFuncAttributeMaxDynamicSharedMemorySize,
                         PROJ_SMEM_BYTES);
    int ptiles = N_NODES_C / 16;                   // 3125
    proj_wmma_kernel<<<(ptiles + PROJ_WARPS - 1) / PROJ_WARPS,
                       PROJ_WARPS * 32, PROJ_SMEM_BYTES>>>();

    // A: alpha stream (2 edges per warp)
    int ablocks = (N_PAIRS_C + 15) / 16;
    alpha_kernel<<<ablocks, 256>>>(w_ij, idx_i, idx_j, phi);

    // B: gather-accumulate
    int nblocks = (N_NODES_C + 7) / 8;
    accum_kernel<<<nblocks, 256>>>(y);

    // overflow (usually empty)
    overflow_kernel<<<1, 256>>>(idx_i, idx_j, y);
}

// round 10
// speedup vs baseline: 1.2749x; 1.0010x over previous
#include <cuda_runtime.h>
#include <cuda_fp16.h>
#include <mma.h>
#include <cstdint>

using namespace nvcuda;

#define N_NODES_C 50000
#define N_PAIRS_C 800000
#define NHEADS_C 4
#define HEAD_DIM_C 64
#define NF_C 256   // NHEADS*HEAD_DIM
#define CAP 96
#define OVF_CAP 4096

// scratch (allocation-free rule: __device__ globals)
__device__ __half g_q[N_NODES_C * NF_C];
__device__ __half g_k[N_NODES_C * NF_C];
__device__ __half g_v[N_NODES_C * NF_C];
__device__ __half g_xh[(size_t)N_NODES_C * NF_C];               // fp16 x
__device__ __half g_wh[3 * NHEADS_C * HEAD_DIM_C * HEAD_DIM_C]; // fp16 W
__device__ float  g_alpha[(size_t)N_PAIRS_C * NHEADS_C];

__device__ int   g_cnt[N_NODES_C];
__device__ int2  g_bkt[(size_t)N_NODES_C * CAP];
__device__ int   g_ovf_cnt;
__device__ int   g_ovf[OVF_CAP];

// ---------------------------------------------------------------------------
// Convert weights to fp16: g_wh[mat*16384 + h*4096 + e*64 + d]
// ---------------------------------------------------------------------------
__global__ void conv_w_kernel(const float* __restrict__ Wq,
                              const float* __restrict__ Wk,
                              const float* __restrict__ Wv) {
    int t = blockIdx.x * blockDim.x + threadIdx.x;
    int base = t * 4;
    if (base >= 3 * 16384) return;
    int mat = base >> 14;
    int r   = base & 16383;
    const float* src = (mat == 0) ? Wq : ((mat == 1) ? Wk : Wv);
    float4 f = *(const float4*)(src + r);
    __half2 h0 = __floats2half2_rn(f.x, f.y);
    __half2 h1 = __floats2half2_rn(f.z, f.w);
    uint2 out;
    out.x = *(const unsigned*)&h0;
    out.y = *(const unsigned*)&h1;
    *(uint2*)(g_wh + mat * 16384 + r) = out;
}

// ---------------------------------------------------------------------------
// Convert x to fp16
// ---------------------------------------------------------------------------
__global__ void conv_x_kernel(const float* __restrict__ x) {
    size_t t = (size_t)blockIdx.x * blockDim.x + threadIdx.x;
    size_t base = t * 8;
    if (base >= (size_t)N_NODES_C * NF_C) return;
    float4 f0 = *(const float4*)(x + base);
    float4 f1 = *(const float4*)(x + base + 4);
    __half2 h0 = __floats2half2_rn(f0.x, f0.y);
    __half2 h1 = __floats2half2_rn(f0.z, f0.w);
    __half2 h2 = __floats2half2_rn(f1.x, f1.y);
    __half2 h3 = __floats2half2_rn(f1.z, f1.w);
    uint4 out;
    out.x = *(const unsigned*)&h0;
    out.y = *(const unsigned*)&h1;
    out.z = *(const unsigned*)&h2;
    out.w = *(const unsigned*)&h3;
    *(uint4*)(g_xh + base) = out;
}

// ---------------------------------------------------------------------------
// Tensor-core projection: warp per 16-node m-tile, W in smem.
// ILP restructure: all 4 et accumulators computed concurrently (kt-outer),
// writeback batched after the mma phase.
// ---------------------------------------------------------------------------
#define PROJ_WARPS 8
#define SMEM_STAGE_F (PROJ_WARPS * 256)
#define SMEM_W_H (3 * NHEADS_C * 64 * 64)      // 49152 halfs
#define PROJ_SMEM_BYTES (SMEM_STAGE_F * 4 + SMEM_W_H * 2)   // 106496 B

__global__ void __launch_bounds__(PROJ_WARPS * 32)
proj_wmma_kernel() {
    extern __shared__ float smraw[];
    float*  stage = smraw;
    __half* sW = (__half*)(smraw + SMEM_STAGE_F);

    int tid  = threadIdx.x;
    int warp = tid >> 5;
    int lane = tid & 31;

    // stage all weights (6144 uint4)
    for (int i = tid; i < SMEM_W_H / 8; i += PROJ_WARPS * 32)
        ((uint4*)sW)[i] = ((const uint4*)g_wh)[i];
    __syncthreads();

    int tile = blockIdx.x * PROJ_WARPS + warp;
    if (tile >= N_NODES_C / 16) return;   // 50000 % 16 == 0
    int n0 = tile * 16;

    const __half* A0 = g_xh + (size_t)n0 * NF_C;
    float* st = stage + warp * 256;
    const int srow = lane >> 1;
    const int sseg = lane & 1;

    for (int h = 0; h < NHEADS_C; h++) {
        wmma::fragment<wmma::matrix_a, 16, 16, 16, __half, wmma::row_major> a[4];
#pragma unroll
        for (int kt = 0; kt < 4; kt++)
            wmma::load_matrix_sync(a[kt], A0 + h * HEAD_DIM_C + kt * 16, NF_C);

        for (int mat = 0; mat < 3; mat++) {
            const __half* Wb = sW + (mat * NHEADS_C + h) * 4096;
            __half* out = (mat == 0) ? g_q : ((mat == 1) ? g_k : g_v);

            // 4 independent accumulator chains (ILP)
            wmma::fragment<wmma::accumulator, 16, 16, 16, float> c[4];
#pragma unroll
            for (int et = 0; et < 4; et++)
                wmma::fill_fragment(c[et], 0.0f);

#pragma unroll
            for (int kt = 0; kt < 4; kt++) {
#pragma unroll
                for (int et = 0; et < 4; et++) {
                    wmma::fragment<wmma::matrix_b, 16, 16, 16, __half, wmma::col_major> b;
                    wmma::load_matrix_sync(b, Wb + et * 16 * 64 + kt * 16, 64);
                    wmma::mma_sync(c[et], a[kt], b, c[et]);
                }
            }

            // batched writeback
#pragma unroll
            for (int et = 0; et < 4; et++) {
                wmma::store_matrix_sync(st, c[et], 16, wmma::mem_row_major);
                __syncwarp();
                const float* src = st + srow * 16 + sseg * 8;
                __half2 o0 = __floats2half2_rn(src[0], src[1]);
                __half2 o1 = __floats2half2_rn(src[2], src[3]);
                __half2 o2 = __floats2half2_rn(src[4], src[5]);
                __half2 o3 = __floats2half2_rn(src[6], src[7]);
                uint4 pack;
                pack.x = *(const unsigned*)&o0;
                pack.y = *(const unsigned*)&o1;
                pack.z = *(const unsigned*)&o2;
                pack.w = *(const unsigned*)&o3;
                *(uint4*)(out + (size_t)(n0 + srow) * NF_C + h * HEAD_DIM_C
                          + et * 16 + sseg * 8) = pack;
                __syncwarp();
            }
        }
    }
}

// ---------------------------------------------------------------------------
// Bucket build
// ---------------------------------------------------------------------------
__global__ void zero_cnt_kernel() {
    int t = blockIdx.x * blockDim.x + threadIdx.x;
    if (t < N_NODES_C) g_cnt[t] = 0;
    if (t == 0) g_ovf_cnt = 0;
}

__global__ void bucket_kernel(const int* __restrict__ idx_i,
                              const int* __restrict__ idx_j) {
    int e = blockIdx.x * blockDim.x + threadIdx.x;
    if (e >= N_PAIRS_C) return;
    int i = idx_i[e];
    int pos = atomicAdd(&g_cnt[i], 1);
    if (pos < CAP) {
        g_bkt[(size_t)i * CAP + pos] = make_int2(e, idx_j[e]);
    } else {
        int p = atomicAdd(&g_ovf_cnt, 1);
        if (p < OVF_CAP) g_ovf[p] = e;
    }
}

// ---------------------------------------------------------------------------
// dot helper
// ---------------------------------------------------------------------------
__device__ __forceinline__ float dot8_h(uint4 qu, uint4 ku, float4 w0, float4 w1) {
    const __half2* q2 = (const __half2*)&qu;
    const __half2* k2 = (const __half2*)&ku;
    float2 qf0 = __half22float2(q2[0]);
    float2 qf1 = __half22float2(q2[1]);
    float2 qf2 = __half22float2(q2[2]);
    float2 qf3 = __half22float2(q2[3]);
    float2 kf0 = __half22float2(k2[0]);
    float2 kf1 = __half22float2(k2[1]);
    float2 kf2 = __half22float2(k2[2]);
    float2 kf3 = __half22float2(k2[3]);
    float s;
    s  = qf0.x * w0.x * kf0.x;
    s += qf0.y * w0.y * kf0.y;
    s += qf1.x * w0.z * kf1.x;
    s += qf1.y * w0.w * kf1.y;
    s += qf2.x * w1.x * kf2.x;
    s += qf2.y * w1.y * kf2.y;
    s += qf3.x * w1.z * kf3.x;
    s += qf3.y * w1.w * kf3.y;
    return s;
}

// ---------------------------------------------------------------------------
// Kernel A: alpha stream (2-edge unroll, measured-good version)
// ---------------------------------------------------------------------------
__global__ void __launch_bounds__(256)
alpha_kernel(const float* __restrict__ w_ij,
             const int* __restrict__ idx_i,
             const int* __restrict__ idx_j,
             const float* __restrict__ phi) {
    int warp = (blockIdx.x * blockDim.x + threadIdx.x) >> 5;
    int lane = threadIdx.x & 31;
    int e0 = warp * 2;
    if (e0 >= N_PAIRS_C) return;
    int e1 = e0 + 1;
    int off = lane * 8;

    int   i0 = __ldg(&idx_i[e0]), i1 = __ldg(&idx_i[e1]);
    int   j0 = __ldg(&idx_j[e0]), j1 = __ldg(&idx_j[e1]);
    float p0 = __ldg(&phi[e0]),   p1 = __ldg(&phi[e1]);

    const float4* wp0 = (const float4*)(w_ij + (size_t)e0 * NF_C + off);
    const float4* wp1 = (const float4*)(w_ij + (size_t)e1 * NF_C + off);
    float4 w00 = __ldcs(wp0);
    float4 w01 = __ldcs(wp0 + 1);
    float4 w10 = __ldcs(wp1);
    float4 w11 = __ldcs(wp1 + 1);

    uint4 qu0 = __ldg((const uint4*)(g_q + (size_t)i0 * NF_C + off));
    uint4 ku0 = __ldg((const uint4*)(g_k + (size_t)j0 * NF_C + off));
    uint4 qu1 = __ldg((const uint4*)(g_q + (size_t)i1 * NF_C + off));
    uint4 ku1 = __ldg((const uint4*)(g_k + (size_t)j1 * NF_C + off));

    float s0 = dot8_h(qu0, ku0, w00, w01);
    float s1 = dot8_h(qu1, ku1, w10, w11);

    s0 += __shfl_xor_sync(0xffffffffu, s0, 1);
    s1 += __shfl_xor_sync(0xffffffffu, s1, 1);
    s0 += __shfl_xor_sync(0xffffffffu, s0, 2);
    s1 += __shfl_xor_sync(0xffffffffu, s1, 2);
    s0 += __shfl_xor_sync(0xffffffffu, s0, 4);
    s1 += __shfl_xor_sync(0xffffffffu, s1, 4);

    if ((lane & 7) == 0) {
        int h = lane >> 3;
        g_alpha[(size_t)e0 * NHEADS_C + h] = s0 * 0.125f * p0;
        g_alpha[(size_t)e1 * NHEADS_C + h] = s1 * 0.125f * p1;
    }
}

// ---------------------------------------------------------------------------
// Kernel B: gather-accumulate (2-edge unroll, measured-good version)
// ---------------------------------------------------------------------------
__global__ void __launch_bounds__(256)
accum_kernel(float* __restrict__ y) {
    int node = (blockIdx.x * blockDim.x + threadIdx.x) >> 5;
    int lane = threadIdx.x & 31;
    if (node >= N_NODES_C) return;

    int deg = g_cnt[node];
    if (deg > CAP) deg = CAP;
    const size_t base = (size_t)node * CAP;
    const int off  = lane * 8;
    const int head = lane >> 3;

    float a0 = 0.f, a1 = 0.f, a2 = 0.f, a3 = 0.f;
    float a4 = 0.f, a5 = 0.f, a6 = 0.f, a7 = 0.f;

    int t = 0;
    for (; t + 2 <= deg; t += 2) {
        int2 m0 = g_bkt[base + t];
        int2 m1 = g_bkt[base + t + 1];
        float al0 = __ldg(&g_alpha[(size_t)m0.x * NHEADS_C + head]);
        float al1 = __ldg(&g_alpha[(size_t)m1.x * NHEADS_C + head]);
        uint4 vu0 = __ldg((const uint4*)(g_v + (size_t)m0.y * NF_C + off));
        uint4 vu1 = __ldg((const uint4*)(g_v + (size_t)m1.y * NF_C + off));

        const __half2* v20 = (const __half2*)&vu0;
        const __half2* v21 = (const __half2*)&vu1;
        float2 f;
        f = __half22float2(v20[0]); a0 = fmaf(al0, f.x, a0); a1 = fmaf(al0, f.y, a1);
        f = __half22float2(v20[1]); a2 = fmaf(al0, f.x, a2); a3 = fmaf(al0, f.y, a3);
        f = __half22float2(v20[2]); a4 = fmaf(al0, f.x, a4); a5 = fmaf(al0, f.y, a5);
        f = __half22float2(v20[3]); a6 = fmaf(al0, f.x, a6); a7 = fmaf(al0, f.y, a7);
        f = __half22float2(v21[0]); a0 = fmaf(al1, f.x, a0); a1 = fmaf(al1, f.y, a1);
        f = __half22float2(v21[1]); a2 = fmaf(al1, f.x, a2); a3 = fmaf(al1, f.y, a3);
        f = __half22float2(v21[2]); a4 = fmaf(al1, f.x, a4); a5 = fmaf(al1, f.y, a5);
        f = __half22float2(v21[3]); a6 = fmaf(al1, f.x, a6); a7 = fmaf(al1, f.y, a7);
    }
    if (t < deg) {
        int2 m0 = g_bkt[base + t];
        float al0 = __ldg(&g_alpha[(size_t)m0.x * NHEADS_C + head]);
        uint4 vu0 = __ldg((const uint4*)(g_v + (size_t)m0.y * NF_C + off));
        const __half2* v20 = (const __half2*)&vu0;
        float2 f;
        f = __half22float2(v20[0]); a0 = fmaf(al0, f.x, a0); a1 = fmaf(al0, f.y, a1);
        f = __half22float2(v20[1]); a2 = fmaf(al0, f.x, a2); a3 = fmaf(al0, f.y, a3);
        f = __half22float2(v20[2]); a4 = fmaf(al0, f.x, a4); a5 = fmaf(al0, f.y, a5);
        f = __half22float2(v20[3]); a6 = fmaf(al0, f.x, a6); a7 = fmaf(al0, f.y, a7);
    }

    float4* yp = (float4*)(y + (size_t)node * NF_C + off);
    yp[0] = make_float4(a0, a1, a2, a3);
    yp[1] = make_float4(a4, a5, a6, a7);
}

// ---------------------------------------------------------------------------
// Overflow fallback
// ---------------------------------------------------------------------------
__global__ void overflow_kernel(const int* __restrict__ idx_i,
                                const int* __restrict__ idx_j,
                                float* __restrict__ y) {
    int n = g_ovf_cnt;
    if (n > OVF_CAP) n = OVF_CAP;
    int lane = threadIdx.x & 31;
    for (int t = (int)(threadIdx.x >> 5); t < n; t += (int)(blockDim.x >> 5)) {
        int e = g_ovf[t];
        int i = idx_i[e];
        int j = idx_j[e];
        int off = lane * 8;
        int head = lane >> 3;

        float alpha = g_alpha[(size_t)e * NHEADS_C + head];
        uint4 vu = *(const uint4*)(g_v + (size_t)j * NF_C + off);
        const __half2* v2 = (const __half2*)&vu;
        float2 f0 = __half22float2(v2[0]);
        float2 f1 = __half22float2(v2[1]);
        float2 f2 = __half22float2(v2[2]);
        float2 f3 = __half22float2(v2[3]);
        float* yp = y + (size_t)i * NF_C + off;
        atomicAdd(yp + 0, alpha * f0.x);
        atomicAdd(yp + 1, alpha * f0.y);
        atomicAdd(yp + 2, alpha * f1.x);
        atomicAdd(yp + 3, alpha * f1.y);
        atomicAdd(yp + 4, alpha * f2.x);
        atomicAdd(yp + 5, alpha * f2.y);
        atomicAdd(yp + 6, alpha * f3.x);
        atomicAdd(yp + 7, alpha * f3.y);
    }
}

// ---------------------------------------------------------------------------
// launch
// ---------------------------------------------------------------------------
extern "C" void kernel_launch(void* const* d_in, const int* in_sizes, int n_in,
                              void* d_out, int out_size) {
    const float* x     = (const float*)d_in[0];
    const float* w_ij  = (const float*)d_in[1];
    const int*   idx_i = (const int*)d_in[2];
    const int*   idx_j = (const int*)d_in[3];
    const float* phi   = (const float*)d_in[4];
    const float* Wq    = (const float*)d_in[5];
    const float* Wk    = (const float*)d_in[6];
    const float* Wv    = (const float*)d_in[7];
    float* y = (float*)d_out;

    // fp16 conversions
    conv_w_kernel<<<48, 256>>>(Wq, Wk, Wv);
    conv_x_kernel<<<6250, 256>>>(x);

    // bucket build
    zero_cnt_kernel<<<(N_NODES_C + 255) / 256, 256>>>();
    bucket_kernel<<<(N_PAIRS_C + 255) / 256, 256>>>(idx_i, idx_j);

    // tensor-core projection (W in smem, 4-way ILP)
    cudaFuncSetAttribute(proj_wmma_kernel,
                         cudaFuncAttributeMaxDynamicSharedMemorySize,
                         PROJ_SMEM_BYTES);
    int ptiles = N_NODES_C / 16;                   // 3125
    proj_wmma_kernel<<<(ptiles + PROJ_WARPS - 1) / PROJ_WARPS,
                       PROJ_WARPS * 32, PROJ_SMEM_BYTES>>>();

    // A: alpha stream (2 edges per warp)
    int ablocks = (N_PAIRS_C + 15) / 16;
    alpha_kernel<<<ablocks, 256>>>(w_ij, idx_i, idx_j, phi);

    // B: gather-accumulate
    int nblocks = (N_NODES_C + 7) / 8;
    accum_kernel<<<nblocks, 256>>>(y);

    // overflow (usually empty)
    overflow_kernel<<<1, 256>>>(idx_i, idx_j, y);
}